// round 2
// baseline (speedup 1.0000x reference)
#include <cuda_runtime.h>
#include <cuda_bf16.h>

// Problem constants (from reference): N=512, B=256, F=400, D=14, K=2
#define GS_B 256
#define GS_F 400
#define GS_D 14
#define GS_DD (GS_D * GS_D)   // 196
#define GS_K 2

// One block per (b,f); 196 threads, one output pixel each.
// All per-(b,f) parameter loads are warp-uniform -> L1 broadcast.
__global__ __launch_bounds__(GS_DD) void GaussianSpot_kernel(
    const int*          __restrict__ batch_idx,   // (B,)
    const unsigned int* __restrict__ m_mask,      // (B,F,K)  bool stored as i32/f32; 0 bits == false
    const float*        __restrict__ height,      // (B,F,K)
    const float*        __restrict__ width,       // (B,F,K)
    const float*        __restrict__ x0,          // (B,F,K)
    const float*        __restrict__ y0,          // (B,F,K)
    const float*        __restrict__ background,  // (B,F)
    const float*        __restrict__ target_locs, // (N,F,2)
    float*              __restrict__ out)         // (B,F,D,D)
{
    const int bf = blockIdx.x;            // b*F + f
    const int t  = threadIdx.x;           // 0..195
    const int b  = bf / GS_F;
    const int f  = bf - b * GS_F;

    // pixel coords: meshgrid 'ij' -> pixel (x, y) at linear index x*D + y
    const int px = t / GS_D;
    const int py = t - px * GS_D;
    const float fx = (float)px;
    const float fy = (float)py;

    const int   bi  = __ldg(&batch_idx[b]);
    const long  tlo = ((long)bi * GS_F + f) * 2;
    const float tlx = __ldg(&target_locs[tlo]);
    const float tly = __ldg(&target_locs[tlo + 1]);

    float acc = __ldg(&background[bf]);

    const float INV_2PI = 0.15915494309189535f;

#pragma unroll
    for (int k = 0; k < GS_K; ++k) {
        const int i = bf * GS_K + k;
        const unsigned int m = __ldg(&m_mask[i]);
        const float h  = (m != 0u) ? __ldg(&height[i]) : 0.0f;
        const float w  = __ldg(&width[i]);
        const float w2 = w * w;
        const float invw2 = __fdividef(1.0f, w2);
        const float sx = tlx + __ldg(&x0[i]);
        const float sy = tly + __ldg(&y0[i]);
        const float dx = fx - sx;
        const float dy = fy - sy;
        const float r2 = fmaf(dx, dx, dy * dy);
        // h * exp(-0.5 r2 / w2) / (2 pi w2)
        const float e = __expf(-0.5f * r2 * invw2);
        acc = fmaf(h * INV_2PI * invw2, e, acc);
    }

    out[(long)bf * GS_DD + t] = acc;
}

extern "C" void kernel_launch(void* const* d_in, const int* in_sizes, int n_in,
                              void* d_out, int out_size) {
    // metadata order: batch_idx, m_mask, height, width, x0, y0, background,
    //                 target_locs, pixel_pos
    const int*          batch_idx   = (const int*)d_in[0];
    const unsigned int* m_mask      = (const unsigned int*)d_in[1];
    const float*        height      = (const float*)d_in[2];
    const float*        width       = (const float*)d_in[3];
    const float*        x0          = (const float*)d_in[4];
    const float*        y0          = (const float*)d_in[5];
    const float*        background  = (const float*)d_in[6];
    const float*        target_locs = (const float*)d_in[7];
    // d_in[8] = pixel_pos: regenerated exactly in-kernel (integer grid)

    float* out = (float*)d_out;

    dim3 grid(GS_B * GS_F);   // 102400 blocks
    dim3 block(GS_DD);        // 196 threads
    GaussianSpot_kernel<<<grid, block>>>(batch_idx, m_mask, height, width,
                                         x0, y0, background, target_locs, out);
}

// round 3
// speedup vs baseline: 3.7354x; 3.7354x over previous
#include <cuda_runtime.h>
#include <cuda_bf16.h>

// Problem constants: N=512, B=256, F=400, D=14, K=2
#define GS_B 256
#define GS_F 400
#define GS_BF (GS_B * GS_F)      // 102400
#define GS_D 14
#define GS_DD (GS_D * GS_D)      // 196
#define GS_K 2

#define BFS_PER_BLOCK 16
#define S2_THREADS (BFS_PER_BLOCK * GS_D)   // 224

typedef unsigned long long ull;

// Per-(b,f) packed parameters: 4 x float4
//  p0 = (sx0, aL0, base2_0, v0_0)
//  p1 = (P0_0, P1_0, V4_0, bg)
//  p2 = (sx1, aL1, base2_1, v0_1)
//  p3 = (P0_1, P1_1, V4_1, 0)
__device__ float4 g_scratch[GS_BF * 4];

__device__ __forceinline__ float ex2f(float x) {
    float y;
    asm("ex2.approx.f32 %0, %1;" : "=f"(y) : "f"(x));
    return y;
}

#define PACK2(d, lo, hi) \
    asm("mov.b64 %0, {%1, %2};" : "=l"(d) : "f"(lo), "f"(hi))
#define MUL2(d, a, b) \
    asm("mul.rn.f32x2 %0, %1, %2;" : "=l"(d) : "l"(a), "l"(b))
#define ADD2(d, a, b) \
    asm("add.rn.f32x2 %0, %1, %2;" : "=l"(d) : "l"(a), "l"(b))

// ---------------- Stage 1: per-(b,f) parameter digest ----------------
__global__ __launch_bounds__(256) void gs_stage1(
    const int*          __restrict__ batch_idx,   // (B,)
    const unsigned int* __restrict__ m_mask,      // (B,F,K)
    const float*        __restrict__ height,      // (B,F,K)
    const float*        __restrict__ width,       // (B,F,K)
    const float*        __restrict__ x0,          // (B,F,K)
    const float*        __restrict__ y0,          // (B,F,K)
    const float*        __restrict__ background,  // (B,F)
    const float*        __restrict__ target_locs) // (N,F,2)
{
    const int bf = blockIdx.x * 256 + threadIdx.x;   // exact: 400*256 = 102400
    const int b  = bf / GS_F;
    const int f  = bf - b * GS_F;

    const int   bi  = __ldg(&batch_idx[b]);
    const int   tlo = (bi * GS_F + f) * 2;
    const float tlx = __ldg(&target_locs[tlo]);
    const float tly = __ldg(&target_locs[tlo + 1]);
    const float bg  = __ldg(&background[bf]);

    const float HALF_LOG2E = 0.7213475204444817f;   // 0.5 * log2(e)
    const float INV_2PI    = 0.15915494309189535f;

#pragma unroll
    for (int k = 0; k < GS_K; ++k) {
        const int i = bf * GS_K + k;
        const unsigned int m = __ldg(&m_mask[i]);
        const float h  = (m != 0u) ? __ldg(&height[i]) : 0.0f;
        const float w  = __ldg(&width[i]);
        const float invw2 = __fdividef(1.0f, w * w);
        const float aL = -HALF_LOG2E * invw2;        // arg scale in log2 domain
        const float c  = h * INV_2PI * invw2;
        const float l2c = __log2f(c);                // c==0 -> -inf (masked spot)
        const float sx = tlx + __ldg(&x0[i]);
        const float sy = tly + __ldg(&y0[i]);

        const float base2 = fmaf(aL * sy, sy, l2c);  // l2c + aL*sy^2
        const float v0 = ex2f(aL * (1.0f - 2.0f * sy));
        const float V  = ex2f(2.0f * aL);
        const float v1 = v0 * V;
        const float v2 = v1 * V;
        const float P0 = v0 * v1;
        const float P1 = v1 * v2;
        const float V2 = V * V;
        const float V4 = V2 * V2;

        g_scratch[bf * 4 + 2 * k]     = make_float4(sx, aL, base2, v0);
        g_scratch[bf * 4 + 2 * k + 1] = make_float4(P0, P1, V4, (k == 0) ? bg : 0.0f);
    }
}

// ---------------- Stage 2: row-recurrence evaluation ----------------
// One thread per (bf, px); computes all 14 y-pixels of its row via the
// packed geometric recurrence, then coalesced store via smem staging.
__global__ __launch_bounds__(S2_THREADS) void gs_stage2(float* __restrict__ out)
{
    __shared__ __align__(16) float sbuf[S2_THREADS * GS_D];   // 224*14 floats

    const int t   = threadIdx.x;          // 0..223
    const int bfl = t / GS_D;             // 0..15
    const int px  = t - bfl * GS_D;       // 0..13
    const int bf  = blockIdx.x * BFS_PER_BLOCK + bfl;

    const float4* pp = &g_scratch[bf * 4];
    const float4 p0 = __ldg(pp + 0);
    const float4 p1 = __ldg(pp + 1);
    const float4 p2 = __ldg(pp + 2);
    const float4 p3 = __ldg(pp + 3);

    const float fpx = (float)px;

    ull A[7];
    ull bgp; PACK2(bgp, p1.w, p1.w);

    // spot 0
    {
        const float dx = fpx - p0.x;
        const float e0 = ex2f(fmaf(p0.y * dx, dx, p0.z));
        const float e1 = e0 * p0.w;
        ull E; PACK2(E, e0, e1);
        ull P; PACK2(P, p1.x, p1.y);
        ull Vp; PACK2(Vp, p1.z, p1.z);
#pragma unroll
        for (int j = 0; j < 7; ++j) {
            ADD2(A[j], bgp, E);
            if (j < 6) { MUL2(E, E, P); MUL2(P, P, Vp); }
        }
    }
    // spot 1
    {
        const float dx = fpx - p2.x;
        const float e0 = ex2f(fmaf(p2.y * dx, dx, p2.z));
        const float e1 = e0 * p2.w;
        ull E; PACK2(E, e0, e1);
        ull P; PACK2(P, p3.x, p3.y);
        ull Vp; PACK2(Vp, p3.z, p3.z);
#pragma unroll
        for (int j = 0; j < 7; ++j) {
            ADD2(A[j], A[j], E);
            if (j < 6) { MUL2(E, E, P); MUL2(P, P, Vp); }
        }
    }

    // stage row into smem (56-byte row start is 8B aligned)
    ull* sp = reinterpret_cast<ull*>(&sbuf[t * GS_D]);
#pragma unroll
    for (int j = 0; j < 7; ++j) sp[j] = A[j];

    __syncthreads();

    // coalesced copy: block writes 16 contiguous images = 3136 floats = 1568 ull
    const ull* sl = reinterpret_cast<const ull*>(sbuf);
    ull* og = reinterpret_cast<ull*>(out) + (size_t)blockIdx.x * (BFS_PER_BLOCK * GS_DD / 2);
#pragma unroll
    for (int j = 0; j < 7; ++j) og[t + S2_THREADS * j] = sl[t + S2_THREADS * j];
}

extern "C" void kernel_launch(void* const* d_in, const int* in_sizes, int n_in,
                              void* d_out, int out_size) {
    const int*          batch_idx   = (const int*)d_in[0];
    const unsigned int* m_mask      = (const unsigned int*)d_in[1];
    const float*        height      = (const float*)d_in[2];
    const float*        width       = (const float*)d_in[3];
    const float*        x0          = (const float*)d_in[4];
    const float*        y0          = (const float*)d_in[5];
    const float*        background  = (const float*)d_in[6];
    const float*        target_locs = (const float*)d_in[7];
    // d_in[8] = pixel_pos: integer grid, regenerated analytically

    float* out = (float*)d_out;

    gs_stage1<<<GS_BF / 256, 256>>>(batch_idx, m_mask, height, width,
                                    x0, y0, background, target_locs);
    gs_stage2<<<GS_BF / BFS_PER_BLOCK, S2_THREADS>>>(out);
}

// round 4
// speedup vs baseline: 4.1347x; 1.1069x over previous
#include <cuda_runtime.h>
#include <cuda_bf16.h>

// Problem constants: N=512, B=256, F=400, D=14, K=2
#define GS_B 256
#define GS_F 400
#define GS_BF (GS_B * GS_F)      // 102400
#define GS_D 14
#define GS_DD (GS_D * GS_D)      // 196
#define GS_K 2

#define BFS 16                    // images per block
#define NT (BFS * GS_D)           // 224 threads

typedef unsigned long long ull;

__device__ __forceinline__ float ex2f(float x) {
    float y;
    asm("ex2.approx.f32 %0, %1;" : "=f"(y) : "f"(x));
    return y;
}

#define PACK2(d, lo, hi) \
    asm("mov.b64 %0, {%1, %2};" : "=l"(d) : "f"(lo), "f"(hi))
#define MUL2(d, a, b) \
    asm("mul.rn.f32x2 %0, %1, %2;" : "=l"(d) : "l"(a), "l"(b))
#define ADD2(d, a, b) \
    asm("add.rn.f32x2 %0, %1, %2;" : "=l"(d) : "l"(a), "l"(b))

// Fused kernel: Phase A computes per-(bf,k) parameter digests into smem,
// Phase B evaluates the 14-pixel row geometric recurrence in packed f32x2,
// stages rows in smem, and writes fully-coalesced 128-bit global stores.
__global__ __launch_bounds__(NT) void gs_fused(
    const int*          __restrict__ batch_idx,   // (B,)
    const unsigned int* __restrict__ m_mask,      // (B,F,K)
    const float*        __restrict__ height,      // (B,F,K)
    const float*        __restrict__ width,       // (B,F,K)
    const float*        __restrict__ x0,          // (B,F,K)
    const float*        __restrict__ y0,          // (B,F,K)
    const float*        __restrict__ background,  // (B,F)
    const float*        __restrict__ target_locs, // (N,F,2)
    float*              __restrict__ out)         // (B,F,D,D)
{
    __shared__ __align__(16) float sparams[BFS][16];   // 1 KB param table
    __shared__ __align__(16) float sbuf[NT * GS_D];    // 12.25 KB staging

    const int t    = threadIdx.x;
    const int wid  = t >> 5;
    const int lane = t & 31;

    // ---- Phase A: 32 (bfl,k) digests, 5 lanes per warp (all SMSPs busy) ----
    const int pidx = wid * 5 + lane;
    if (lane < 5 && pidx < 2 * BFS) {
        const int bfl = pidx >> 1;
        const int k   = pidx & 1;
        const int bf  = blockIdx.x * BFS + bfl;
        const int b   = bf / GS_F;
        const int f   = bf - b * GS_F;

        const int   bi  = __ldg(&batch_idx[b]);
        const int   tlo = (bi * GS_F + f) * 2;
        const float tlx = __ldg(&target_locs[tlo]);
        const float tly = __ldg(&target_locs[tlo + 1]);

        const int i = bf * GS_K + k;
        const unsigned int m = __ldg(&m_mask[i]);
        const float h  = (m != 0u) ? __ldg(&height[i]) : 0.0f;
        const float w  = __ldg(&width[i]);
        const float invw2 = __fdividef(1.0f, w * w);

        const float HALF_LOG2E = 0.7213475204444817f;   // 0.5*log2(e)
        const float INV_2PI    = 0.15915494309189535f;

        const float aL  = -HALF_LOG2E * invw2;           // log2-domain scale
        const float l2c = __log2f(h * INV_2PI * invw2);  // h==0 -> -inf -> e==0
        const float sx  = tlx + __ldg(&x0[i]);
        const float sy  = tly + __ldg(&y0[i]);

        const float base2 = fmaf(aL * sy, sy, l2c);
        const float v0 = ex2f(aL * (1.0f - 2.0f * sy));
        const float V  = ex2f(2.0f * aL);
        const float v1 = v0 * V;
        const float v2 = v1 * V;
        const float V2 = V * V;
        const float bgv = (k == 0) ? __ldg(&background[bf]) : 0.0f;

        float4* row = reinterpret_cast<float4*>(&sparams[bfl][8 * k]);
        row[0] = make_float4(sx, aL, base2, v0);
        row[1] = make_float4(v0 * v1, v1 * v2, V2 * V2, bgv);
    }
    __syncthreads();

    // ---- Phase B: packed row recurrence ----
    const int bfl = t / GS_D;             // 0..15
    const int px  = t - bfl * GS_D;       // 0..13
    const float4* pp = reinterpret_cast<const float4*>(sparams[bfl]);
    const float4 p0 = pp[0];
    const float4 p1 = pp[1];
    const float4 p2 = pp[2];
    const float4 p3 = pp[3];

    const float fpx = (float)px;

    ull A[7];
    ull bgp; PACK2(bgp, p1.w, p1.w);

    // spot 0
    {
        const float dx = fpx - p0.x;
        const float e0 = ex2f(fmaf(p0.y * dx, dx, p0.z));
        const float e1 = e0 * p0.w;
        ull E; PACK2(E, e0, e1);
        ull P; PACK2(P, p1.x, p1.y);
        ull Vp; PACK2(Vp, p1.z, p1.z);
#pragma unroll
        for (int j = 0; j < 7; ++j) {
            ADD2(A[j], bgp, E);
            if (j < 6) { MUL2(E, E, P); MUL2(P, P, Vp); }
        }
    }
    // spot 1
    {
        const float dx = fpx - p2.x;
        const float e0 = ex2f(fmaf(p2.y * dx, dx, p2.z));
        const float e1 = e0 * p2.w;
        ull E; PACK2(E, e0, e1);
        ull P; PACK2(P, p3.x, p3.y);
        ull Vp; PACK2(Vp, p3.z, p3.z);
#pragma unroll
        for (int j = 0; j < 7; ++j) {
            ADD2(A[j], A[j], E);
            if (j < 6) { MUL2(E, E, P); MUL2(P, P, Vp); }
        }
    }

    // stage row into smem (row start = t*56 bytes, 8B aligned)
    ull* sp = reinterpret_cast<ull*>(&sbuf[t * GS_D]);
#pragma unroll
    for (int j = 0; j < 7; ++j) sp[j] = A[j];

    __syncthreads();

    // ---- coalesced 128-bit writeout: 784 uint4 per block = 3*224 + 112 ----
    const uint4* sl = reinterpret_cast<const uint4*>(sbuf);
    uint4* og = reinterpret_cast<uint4*>(out) + (size_t)blockIdx.x * (BFS * GS_DD / 4);
#pragma unroll
    for (int j = 0; j < 3; ++j) og[t + NT * j] = sl[t + NT * j];
    if (t < 112) og[t + NT * 3] = sl[t + NT * 3];
}

extern "C" void kernel_launch(void* const* d_in, const int* in_sizes, int n_in,
                              void* d_out, int out_size) {
    const int*          batch_idx   = (const int*)d_in[0];
    const unsigned int* m_mask      = (const unsigned int*)d_in[1];
    const float*        height      = (const float*)d_in[2];
    const float*        width       = (const float*)d_in[3];
    const float*        x0          = (const float*)d_in[4];
    const float*        y0          = (const float*)d_in[5];
    const float*        background  = (const float*)d_in[6];
    const float*        target_locs = (const float*)d_in[7];
    // d_in[8] = pixel_pos: integer grid, regenerated analytically

    float* out = (float*)d_out;

    gs_fused<<<GS_BF / BFS, NT>>>(batch_idx, m_mask, height, width,
                                  x0, y0, background, target_locs, out);
}